// round 4
// baseline (speedup 1.0000x reference)
#include <cuda_runtime.h>
#include <cstdint>

// ============================================================================
// MultiLoraLinear (base-ISA path: mma.sync.m16n8k8.tf32 + cp.async)
//   out = x @ W^T + bias + LoRA(per-segment, rank 16)
//
//   1) sel_kernel : batch -> weight id (0 = none, 1..3 = adapters)
//                   DTYPE-ROBUST read of lora_start_indices (i32 OR i64 —
//                   JAX x64-off silently emits int32!)
//   2) wr_kernel  : W rounded to tf32 (RN)           -> g_wr   (64 MB)
//   3) bwx_kernel : [lora_B_a | 0] tf32, slab0=zeros -> g_bwx  (2 MB)
//   4) xa_kernel  : g_xr = rtf32(x); g_xa = [rtf32(x @ A_sel^T) | 0]
//   5) gemm_kernel: 128x256 CTA tiles, K = 129 chunks of 32 (last = LoRA ext),
//      2-stage cp.async pipeline, fused bias epilogue.
// ============================================================================

#define DIN      4096
#define DOUT     4096
#define NBATCH   8
#define MROWS    16384
#define RANK     16
#define NLORA    3
#define SCALE_F  1.0f                // alpha / rank

#define BM       128
#define BN       256
#define BK       32
#define NCH      (DIN / BK)          // 128 main chunks
#define NCHT     (NCH + 1)           // +1 LoRA extension chunk
#define GTHREADS 256

// SMEM layout in floats: bias[256] | A[2][128*36] | B[2][256*36]
#define ROWF     36
#define SM_BIAS  0
#define SM_A     256
#define A_STGF   (BM * ROWF)         // 4608
#define SM_B     (SM_A + 2 * A_STGF)
#define B_STGF   (BN * ROWF)         // 9216
#define SMEM_FLOATS (SM_B + 2 * B_STGF)
#define SMEM_BYTES  (SMEM_FLOATS * 4)   // 111616

// ---------------------------------------------------------------------------
// device scratch (no cudaMalloc allowed)
// ---------------------------------------------------------------------------
__device__ float g_wr[(size_t)DOUT * DIN];            // 64 MB
__device__ float g_xr[(size_t)MROWS * DIN];           // 256 MB
__device__ float g_xa[(size_t)MROWS * 32];            // 2 MB  [xa(16)|0(16)]
__device__ float g_bwx[(size_t)(NLORA + 1) * DOUT * 32];  // 2 MB
__device__ int   g_sel[NBATCH];

// ---------------------------------------------------------------------------
// helpers
// ---------------------------------------------------------------------------
__device__ __forceinline__ uint32_t smem_u32(const void* p) {
    uint32_t a;
    asm("{ .reg .u64 t; cvta.to.shared.u64 t, %1; cvt.u32.u64 %0, t; }"
        : "=r"(a) : "l"(p));
    return a;
}

__device__ __forceinline__ float rtf32(float f) {
    uint32_t u;
    asm("cvt.rna.tf32.f32 %0, %1;" : "=r"(u) : "f"(f));
    return __uint_as_float(u);
}

__device__ __forceinline__ void cp_async16(uint32_t dst_smem, const void* src) {
    asm volatile("cp.async.cg.shared.global [%0], [%1], 16;"
                 :: "r"(dst_smem), "l"(src) : "memory");
}
#define CP_COMMIT() asm volatile("cp.async.commit_group;" ::: "memory")
#define CP_WAIT1()  asm volatile("cp.async.wait_group 1;" ::: "memory")
#define CP_WAIT0()  asm volatile("cp.async.wait_group 0;" ::: "memory")

__device__ __forceinline__ void mma_tf32(float* d, uint32_t a0, uint32_t a1,
                                         uint32_t a2, uint32_t a3,
                                         uint32_t b0, uint32_t b1) {
    asm volatile(
        "mma.sync.aligned.m16n8k8.row.col.f32.tf32.tf32.f32 "
        "{%0,%1,%2,%3}, {%4,%5,%6,%7}, {%8,%9}, {%0,%1,%2,%3};"
        : "+f"(d[0]), "+f"(d[1]), "+f"(d[2]), "+f"(d[3])
        : "r"(a0), "r"(a1), "r"(a2), "r"(a3), "r"(b0), "r"(b1));
}

// ---------------------------------------------------------------------------
// 1) batch -> weight id.  searchsorted(starts, b, 'right') - 1 semantics.
//    DTYPE-ROBUST: JAX with x64 disabled emits int32 even when the reference
//    asks for int64.  Try the int64 view; if implausible, use int32.
// ---------------------------------------------------------------------------
__global__ void sel_kernel(const void* __restrict__ starts_raw, int n_starts) {
    const long long* s64 = (const long long*)starts_raw;
    const int*       s32 = (const int*)starts_raw;

    // plausibility of int64 view: nonneg, < 64, nondecreasing
    bool ok64 = true;
    long long prev = -1;
    for (int j = 0; j < n_starts; j++) {
        long long v = s64[j];
        if (v < 0 || v >= 64 || v < prev) { ok64 = false; break; }
        prev = v;
    }

    int b = threadIdx.x;
    if (b < NBATCH) {
        int cnt = 0;
        for (int j = 0; j < n_starts; j++) {
            long long v = ok64 ? s64[j] : (long long)s32[j];
            cnt += (v <= (long long)b);
        }
        int seg = cnt - 1;                 // 0 = no LoRA
        int id = 0;
        if (seg > 0) { id = seg; if (id > NLORA) id = NLORA; }
        g_sel[b] = id;
    }
}

// ---------------------------------------------------------------------------
// 2) W -> tf32 copy
// ---------------------------------------------------------------------------
__global__ void __launch_bounds__(256) wr_kernel(const float* __restrict__ W) {
    size_t idx = (size_t)blockIdx.x * 256 + threadIdx.x;
    float4 v = ((const float4*)W)[idx];
    v.x = rtf32(v.x); v.y = rtf32(v.y); v.z = rtf32(v.z); v.w = rtf32(v.w);
    ((float4*)g_wr)[idx] = v;
}

// ---------------------------------------------------------------------------
// 3) B-extension table: g_bwx[a][n][c] = (a>0 && c<16) ? rtf32(lora_B[a-1][n][c]) : 0
// ---------------------------------------------------------------------------
__global__ void __launch_bounds__(256) bwx_kernel(const float* __restrict__ lB) {
    int idx = blockIdx.x * 256 + threadIdx.x;   // < 4*4096*32 = 524288
    int c = idx & 31;
    int n = (idx >> 5) & (DOUT - 1);
    int a = idx >> 17;
    float v = 0.0f;
    if (a > 0 && c < RANK)
        v = rtf32(lB[((size_t)(a - 1) * DOUT + n) * RANK + c]);
    g_bwx[idx] = v;
}

// ---------------------------------------------------------------------------
// 4) per-row: g_xr = rtf32(x row); g_xa = [rtf32(scale * x @ A_sel^T) | 0]
// ---------------------------------------------------------------------------
__global__ void __launch_bounds__(128) xa_kernel(const float* __restrict__ x,
                                                 const float* __restrict__ lA) {
    __shared__ float part[RANK][136];
    const int m   = blockIdx.x;
    const int tid = threadIdx.x;
    const int sel = g_sel[m >> 11];
    const float* xrow = x + (size_t)m * DIN;

    float acc[RANK];
#pragma unroll
    for (int r = 0; r < RANK; r++) acc[r] = 0.0f;

    if (sel > 0) {
        const float* A = lA + (size_t)(sel - 1) * RANK * DIN;
        for (int d = tid; d < DIN; d += 128) {
            float xv = xrow[d];
            g_xr[(size_t)m * DIN + d] = rtf32(xv);
#pragma unroll
            for (int r = 0; r < RANK; r++) acc[r] += xv * A[(size_t)r * DIN + d];
        }
    } else {
        for (int d = tid; d < DIN; d += 128)
            g_xr[(size_t)m * DIN + d] = rtf32(xrow[d]);
    }

#pragma unroll
    for (int r = 0; r < RANK; r++) part[r][tid] = acc[r];
    __syncthreads();
    for (int s = 64; s > 0; s >>= 1) {
        if (tid < s) {
#pragma unroll
            for (int r = 0; r < RANK; r++) part[r][tid] += part[r][tid + s];
        }
        __syncthreads();
    }
    if (tid < RANK)
        g_xa[(size_t)m * 32 + tid] = rtf32(part[tid][0] * SCALE_F);
    else if (tid < 32)
        g_xa[(size_t)m * 32 + tid] = 0.0f;
}

// ---------------------------------------------------------------------------
// 5) GEMM: out[m,n] = sum_{129 chunks} A_chunk . B_chunk + bias[n]
// ---------------------------------------------------------------------------
__global__ void __launch_bounds__(GTHREADS, 1)
gemm_kernel(const float* __restrict__ bias, float* __restrict__ out) {
    extern __shared__ float smf[];
    const int tid  = threadIdx.x;
    const int lane = tid & 31;
    const int wid  = tid >> 5;
    const int gid  = lane >> 2;
    const int tig  = lane & 3;
    const int wm   = wid & 1;
    const int wn   = wid >> 1;

    const int n0 = blockIdx.x * BN;
    const int m0 = blockIdx.y * BM;
    const int sel = g_sel[m0 >> 11];

    smf[SM_BIAS + tid] = bias[n0 + tid];

    const uint32_t sbase = smem_u32(smf);
    const int rowA = tid >> 3;         // 0..31 (+32*i)
    const int q    = tid & 7;          // float4 slot within 32-float row
    const float* srcA  = g_xr + (size_t)(m0 + rowA) * DIN + q * 4;
    const float* srcB  = g_wr + (size_t)(n0 + rowA) * DIN + q * 4;
    const float* srcAe = g_xa  + (size_t)(m0 + rowA) * 32 + q * 4;
    const float* srcBe = g_bwx + ((size_t)sel * DOUT + (n0 + rowA)) * 32 + q * 4;
    const uint32_t dstA = sbase + (SM_A + rowA * ROWF + q * 4) * 4u;
    const uint32_t dstB = sbase + (SM_B + rowA * ROWF + q * 4) * 4u;

#define PREFETCH(cn, s) do {                                                  \
    if ((cn) < NCH) {                                                         \
        const int _kb = (cn) * BK;                                            \
        _Pragma("unroll")                                                     \
        for (int i = 0; i < 4; i++)                                           \
            cp_async16(dstA + (s) * (A_STGF * 4) + i * (32 * ROWF * 4),       \
                       srcA + (size_t)(32 * i) * DIN + _kb);                  \
        _Pragma("unroll")                                                     \
        for (int i = 0; i < 8; i++)                                           \
            cp_async16(dstB + (s) * (B_STGF * 4) + i * (32 * ROWF * 4),       \
                       srcB + (size_t)(32 * i) * DIN + _kb);                  \
    } else {                                                                  \
        _Pragma("unroll")                                                     \
        for (int i = 0; i < 4; i++)                                           \
            cp_async16(dstA + (s) * (A_STGF * 4) + i * (32 * ROWF * 4),       \
                       srcAe + (size_t)(32 * i) * 32);                        \
        _Pragma("unroll")                                                     \
        for (int i = 0; i < 8; i++)                                           \
            cp_async16(dstB + (s) * (B_STGF * 4) + i * (32 * ROWF * 4),       \
                       srcBe + (size_t)(32 * i) * 32);                        \
    }                                                                         \
} while (0)

    PREFETCH(0, 0); CP_COMMIT();
    PREFETCH(1, 1); CP_COMMIT();

    float d[4][8][4];
#pragma unroll
    for (int mt = 0; mt < 4; mt++)
#pragma unroll
        for (int nt = 0; nt < 8; nt++)
#pragma unroll
            for (int r = 0; r < 4; r++) d[mt][nt][r] = 0.0f;

    for (int c = 0; c < NCHT; c++) {
        const int s = c & 1;
        CP_WAIT1();
        __syncthreads();

        const uint32_t* As = (const uint32_t*)(smf + SM_A + s * A_STGF);
        const uint32_t* Bs = (const uint32_t*)(smf + SM_B + s * B_STGF);

#pragma unroll
        for (int kk = 0; kk < 4; kk++) {
            const int k0 = kk * 8;
            uint32_t a[4][4];
#pragma unroll
            for (int mt = 0; mt < 4; mt++) {
                const int r = wm * 64 + mt * 16 + gid;
                a[mt][0] = As[(r)     * ROWF + k0 + tig];
                a[mt][1] = As[(r + 8) * ROWF + k0 + tig];
                a[mt][2] = As[(r)     * ROWF + k0 + tig + 4];
                a[mt][3] = As[(r + 8) * ROWF + k0 + tig + 4];
            }
            uint32_t b[8][2];
#pragma unroll
            for (int nt = 0; nt < 8; nt++) {
                const int nr = wn * 64 + nt * 8 + gid;
                b[nt][0] = Bs[nr * ROWF + k0 + tig];
                b[nt][1] = Bs[nr * ROWF + k0 + tig + 4];
            }
#pragma unroll
            for (int mt = 0; mt < 4; mt++)
#pragma unroll
                for (int nt = 0; nt < 8; nt++)
                    mma_tf32(d[mt][nt], a[mt][0], a[mt][1], a[mt][2], a[mt][3],
                             b[nt][0], b[nt][1]);
        }

        __syncthreads();
        // clamped prefetch: never an empty commit group (exact wait accounting)
        int cn = c + 2; if (cn > NCH) cn = NCH;
        PREFETCH(cn, s);
        CP_COMMIT();
    }
    CP_WAIT0();

    // ---- epilogue: fused bias ----
    const float* bs = smf + SM_BIAS + wn * 64;
#pragma unroll
    for (int mt = 0; mt < 4; mt++) {
        const int r = m0 + wm * 64 + mt * 16 + gid;
        float* o0p = out + (size_t)r * DOUT + n0 + wn * 64;
        float* o1p = o0p + (size_t)8 * DOUT;
#pragma unroll
        for (int nt = 0; nt < 8; nt++) {
            const int col = nt * 8 + tig * 2;
            float2 v0, v1;
            v0.x = d[mt][nt][0] + bs[col];
            v0.y = d[mt][nt][1] + bs[col + 1];
            v1.x = d[mt][nt][2] + bs[col];
            v1.y = d[mt][nt][3] + bs[col + 1];
            *(float2*)(o0p + col) = v0;
            *(float2*)(o1p + col) = v1;
        }
    }
#undef PREFETCH
}

// ---------------------------------------------------------------------------
// launch
// ---------------------------------------------------------------------------
extern "C" void kernel_launch(void* const* d_in, const int* in_sizes, int n_in,
                              void* d_out, int out_size) {
    const float* x      = (const float*)d_in[0];
    const float* weight = (const float*)d_in[1];
    const float* bias   = (const float*)d_in[2];
    const float* lora_A = (const float*)d_in[3];
    const float* lora_B = (const float*)d_in[4];
    const void*  starts = d_in[5];
    float* out = (float*)d_out;
    const int n_starts = in_sizes[5];

    sel_kernel<<<1, 32>>>(starts, n_starts);
    wr_kernel<<<(DOUT * (size_t)DIN / 4) / 256, 256>>>(weight);
    bwx_kernel<<<((NLORA + 1) * DOUT * 32) / 256, 256>>>(lora_B);
    xa_kernel<<<MROWS, 128>>>(x, lora_A);

    cudaFuncSetAttribute(gemm_kernel,
                         cudaFuncAttributeMaxDynamicSharedMemorySize, SMEM_BYTES);
    dim3 grid(DOUT / BN, MROWS / BM);  // (16, 128)
    gemm_kernel<<<grid, GTHREADS, SMEM_BYTES>>>(bias, out);
}

// round 5
// speedup vs baseline: 1.8463x; 1.8463x over previous
#include <cuda_runtime.h>
#include <cuda_fp16.h>
#include <cstdint>

// ============================================================================
// MultiLoraLinear — fp16 HMMA path (mma.sync.m16n8k16.f16.f32 + cp.async)
//   out = x @ W^T + bias + LoRA(per-segment, rank 16)
//
// fp16 and tf32 have the SAME 10-bit mantissa -> same accuracy as the
// passing tf32 kernel (measured 2.94e-4), but K=16 per MMA instruction:
// half the tensor ops, half the SMEM/LTS traffic.
//
//   1) sel_kernel : batch -> weight id (dtype-robust starts read: i32 or i64)
//   2) wh_kernel  : W -> half RN                      -> g_wh  (32 MB)
//   3) bwhx_kernel: [lora_B_a | 0] half, slab0=zeros  -> g_bwhx (2 MB)
//   4) xa_kernel  : g_xh = half(x); g_xah = [half(x @ A_sel^T) | 0]
//   5) gemm_kernel: 128x256 CTA tiles, K = 65 chunks of 64 halves (last =
//      LoRA ext), 3-stage cp.async pipeline, ONE barrier per chunk,
//      prefetch-at-top, fused bias epilogue.
// ============================================================================

#define DIN      4096
#define DOUT     4096
#define NBATCH   8
#define MROWS    16384
#define RANK     16
#define NLORA    3
#define SCALE_F  1.0f                // alpha / rank

#define BM       128
#define BN       256
#define BKH      64                  // K halves per chunk (= 128 B per row)
#define NCH      (DIN / BKH)         // 64 main chunks
#define NCHT     (NCH + 1)           // +1 LoRA extension chunk
#define GTHREADS 256

// SMEM layout (bytes): bias 256 floats | 3x A stage | 3x B stage
#define ROWB     144                 // padded row stride bytes (72 halves)
#define OFF_A    1024
#define A_STGB   (BM * ROWB)         // 18432
#define OFF_B    (OFF_A + 3 * A_STGB)
#define B_STGB   (BN * ROWB)         // 36864
#define SMEM_BYTES (OFF_B + 3 * B_STGB)   // 166912

// ---------------------------------------------------------------------------
// device scratch (no cudaMalloc allowed)
// ---------------------------------------------------------------------------
__device__ __half g_wh[(size_t)DOUT * DIN];               // 32 MB
__device__ __half g_xh[(size_t)MROWS * DIN];              // 128 MB
__device__ __half g_xah[(size_t)MROWS * BKH];             // 2 MB  [xa(16)|0(48)]
__device__ __half g_bwhx[(size_t)(NLORA + 1) * DOUT * BKH];  // 2 MB
__device__ int    g_sel[NBATCH];

// ---------------------------------------------------------------------------
// helpers
// ---------------------------------------------------------------------------
__device__ __forceinline__ uint32_t smem_u32(const void* p) {
    uint32_t a;
    asm("{ .reg .u64 t; cvta.to.shared.u64 t, %1; cvt.u32.u64 %0, t; }"
        : "=r"(a) : "l"(p));
    return a;
}

__device__ __forceinline__ void cp_async16(uint32_t dst_smem, const void* src) {
    asm volatile("cp.async.cg.shared.global [%0], [%1], 16;"
                 :: "r"(dst_smem), "l"(src) : "memory");
}
#define CP_COMMIT() asm volatile("cp.async.commit_group;" ::: "memory")
#define CP_WAIT1()  asm volatile("cp.async.wait_group 1;" ::: "memory")
#define CP_WAIT0()  asm volatile("cp.async.wait_group 0;" ::: "memory")

__device__ __forceinline__ void mma_f16(float* d, uint32_t a0, uint32_t a1,
                                        uint32_t a2, uint32_t a3,
                                        uint32_t b0, uint32_t b1) {
    asm volatile(
        "mma.sync.aligned.m16n8k16.row.col.f32.f16.f16.f32 "
        "{%0,%1,%2,%3}, {%4,%5,%6,%7}, {%8,%9}, {%0,%1,%2,%3};"
        : "+f"(d[0]), "+f"(d[1]), "+f"(d[2]), "+f"(d[3])
        : "r"(a0), "r"(a1), "r"(a2), "r"(a3), "r"(b0), "r"(b1));
}

// ---------------------------------------------------------------------------
// 1) batch -> weight id.  searchsorted(starts, b, 'right') - 1 semantics.
//    DTYPE-ROBUST: JAX with x64 disabled emits int32 even for "int64".
// ---------------------------------------------------------------------------
__global__ void sel_kernel(const void* __restrict__ starts_raw, int n_starts) {
    const long long* s64 = (const long long*)starts_raw;
    const int*       s32 = (const int*)starts_raw;

    bool ok64 = true;
    long long prev = -1;
    for (int j = 0; j < n_starts; j++) {
        long long v = s64[j];
        if (v < 0 || v >= 64 || v < prev) { ok64 = false; break; }
        prev = v;
    }

    int b = threadIdx.x;
    if (b < NBATCH) {
        int cnt = 0;
        for (int j = 0; j < n_starts; j++) {
            long long v = ok64 ? s64[j] : (long long)s32[j];
            cnt += (v <= (long long)b);
        }
        int seg = cnt - 1;
        int id = 0;
        if (seg > 0) { id = seg; if (id > NLORA) id = NLORA; }
        g_sel[b] = id;
    }
}

// ---------------------------------------------------------------------------
// 2) W -> half (RN).  8 floats per thread.
// ---------------------------------------------------------------------------
__global__ void __launch_bounds__(256) wh_kernel(const float* __restrict__ W) {
    size_t idx = (size_t)blockIdx.x * 256 + threadIdx.x;      // 8-float group
    const float4* W4 = (const float4*)W;
    float4 a = W4[2 * idx], b = W4[2 * idx + 1];
    __half2 h[4];
    h[0] = __floats2half2_rn(a.x, a.y);
    h[1] = __floats2half2_rn(a.z, a.w);
    h[2] = __floats2half2_rn(b.x, b.y);
    h[3] = __floats2half2_rn(b.z, b.w);
    *(uint4*)(g_wh + idx * 8) = *(const uint4*)h;
}

// ---------------------------------------------------------------------------
// 3) B-extension: g_bwhx[a][n][c] = (a>0 && c<16) ? half(lora_B[a-1][n][c]) : 0
// ---------------------------------------------------------------------------
__global__ void __launch_bounds__(256) bwhx_kernel(const float* __restrict__ lB) {
    int idx = blockIdx.x * 256 + threadIdx.x;   // < 4*4096*64 = 1048576
    int c = idx & 63;
    int n = (idx >> 6) & (DOUT - 1);
    int a = idx >> 18;
    float v = 0.0f;
    if (a > 0 && c < RANK)
        v = lB[((size_t)(a - 1) * DOUT + n) * RANK + c];
    g_bwhx[idx] = __float2half_rn(v);
}

// ---------------------------------------------------------------------------
// 4) per-row: g_xh = half(x row); g_xah = [half(scale * x @ A_sel^T) | 0]
//    128 threads/row, float4 loads, warp-shuffle reduction.
// ---------------------------------------------------------------------------
__global__ void __launch_bounds__(128) xa_kernel(const float* __restrict__ x,
                                                 const float* __restrict__ lA) {
    __shared__ float part[RANK][4];
    const int m   = blockIdx.x;
    const int tid = threadIdx.x;
    const int sel = g_sel[m >> 11];
    const float4* xr = (const float4*)(x + (size_t)m * DIN);
    const float4* A4 = (const float4*)(lA + (size_t)(sel > 0 ? sel - 1 : 0) * RANK * DIN);

    float acc[RANK];
#pragma unroll
    for (int r = 0; r < RANK; r++) acc[r] = 0.0f;

#pragma unroll
    for (int it = 0; it < 4; it++) {
        const int f4 = it * 256 + tid * 2;          // float4 index (even)
        float4 v0 = xr[f4], v1 = xr[f4 + 1];
        __half2 h[4];
        h[0] = __floats2half2_rn(v0.x, v0.y);
        h[1] = __floats2half2_rn(v0.z, v0.w);
        h[2] = __floats2half2_rn(v1.x, v1.y);
        h[3] = __floats2half2_rn(v1.z, v1.w);
        *(uint4*)(g_xh + (size_t)m * DIN + f4 * 4) = *(const uint4*)h;

        if (sel > 0) {
#pragma unroll
            for (int r = 0; r < RANK; r++) {
                float4 a0 = A4[r * (DIN / 4) + f4];
                float4 a1 = A4[r * (DIN / 4) + f4 + 1];
                acc[r] += v0.x * a0.x + v0.y * a0.y + v0.z * a0.z + v0.w * a0.w
                        + v1.x * a1.x + v1.y * a1.y + v1.z * a1.z + v1.w * a1.w;
            }
        }
    }

#pragma unroll
    for (int r = 0; r < RANK; r++) {
#pragma unroll
        for (int off = 16; off > 0; off >>= 1)
            acc[r] += __shfl_xor_sync(0xffffffffu, acc[r], off);
    }
    const int wrp = tid >> 5, ln = tid & 31;
    if (ln == 0) {
#pragma unroll
        for (int r = 0; r < RANK; r++) part[r][wrp] = acc[r];
    }
    __syncthreads();
    if (tid < RANK) {
        float s = part[tid][0] + part[tid][1] + part[tid][2] + part[tid][3];
        g_xah[(size_t)m * BKH + tid] = __float2half_rn(s * SCALE_F);
    } else if (tid < BKH) {
        g_xah[(size_t)m * BKH + tid] = __float2half_rn(0.0f);
    }
}

// ---------------------------------------------------------------------------
// 5) GEMM: out[m,n] = sum_{65 chunks of 64 halves} A.B + bias[n]
//    3-stage pipeline, one barrier per chunk, prefetch-at-top.
// ---------------------------------------------------------------------------
__global__ void __launch_bounds__(GTHREADS, 1)
gemm_kernel(const float* __restrict__ bias, float* __restrict__ out) {
    extern __shared__ char smem[];
    float* smf = (float*)smem;
    const int tid  = threadIdx.x;
    const int lane = tid & 31;
    const int wid  = tid >> 5;
    const int gid  = lane >> 2;      // 0..7
    const int tig  = lane & 3;       // 0..3
    const int wm   = wid & 1;        // warp M (2)
    const int wn   = wid >> 1;       // warp N (4)

    const int n0 = blockIdx.x * BN;
    const int m0 = blockIdx.y * BM;
    const int sel = g_sel[m0 >> 11];

    smf[tid] = bias[n0 + tid];       // bias in bytes [0,1024)

    const uint32_t sbase = smem_u32(smem);
    const int rowA = tid >> 3;       // 0..31 (+32*i)
    const int q    = tid & 7;        // 16B slot within 128B row
    const __half* srcA  = g_xh + (size_t)(m0 + rowA) * DIN + q * 8;
    const __half* srcB  = g_wh + (size_t)(n0 + rowA) * DIN + q * 8;
    const __half* srcAe = g_xah  + (size_t)(m0 + rowA) * BKH + q * 8;
    const __half* srcBe = g_bwhx + ((size_t)sel * DOUT + (n0 + rowA)) * BKH + q * 8;
    const uint32_t dstA = sbase + OFF_A + (uint32_t)(rowA * ROWB + q * 16);
    const uint32_t dstB = sbase + OFF_B + (uint32_t)(rowA * ROWB + q * 16);

#define PREFETCH(cn, st) do {                                                 \
    if ((cn) < NCH) {                                                         \
        const __half* _a = srcA + (size_t)(cn) * BKH;                         \
        const __half* _b = srcB + (size_t)(cn) * BKH;                         \
        _Pragma("unroll")                                                     \
        for (int i = 0; i < 4; i++)                                           \
            cp_async16(dstA + (st) * A_STGB + i * (32 * ROWB),                \
                       _a + (size_t)(32 * i) * DIN);                          \
        _Pragma("unroll")                                                     \
        for (int i = 0; i < 8; i++)                                           \
            cp_async16(dstB + (st) * B_STGB + i * (32 * ROWB),                \
                       _b + (size_t)(32 * i) * DIN);                          \
    } else {                                                                  \
        _Pragma("unroll")                                                     \
        for (int i = 0; i < 4; i++)                                           \
            cp_async16(dstA + (st) * A_STGB + i * (32 * ROWB),                \
                       srcAe + (size_t)(32 * i) * BKH);                       \
        _Pragma("unroll")                                                     \
        for (int i = 0; i < 8; i++)                                           \
            cp_async16(dstB + (st) * B_STGB + i * (32 * ROWB),                \
                       srcBe + (size_t)(32 * i) * BKH);                       \
    }                                                                         \
} while (0)

    PREFETCH(0, 0); CP_COMMIT();
    PREFETCH(1, 1); CP_COMMIT();

    float d[4][8][4];
#pragma unroll
    for (int mt = 0; mt < 4; mt++)
#pragma unroll
        for (int nt = 0; nt < 8; nt++)
#pragma unroll
            for (int r = 0; r < 4; r++) d[mt][nt][r] = 0.0f;

    for (int c = 0; c < NCHT; c++) {
        const int st = c % 3;
        CP_WAIT1();                   // chunk c's group complete
        __syncthreads();              // all warps done with stage (c-1)%3

        // prefetch chunk c+2 into stage (c+2)%3 (clamped duplicate at tail
        // keeps cp.async group accounting exact; dead stages never read)
        {
            int cn = c + 2; if (cn > NCH) cn = NCH;
            const int stp = (c + 2) % 3;
            PREFETCH(cn, stp);
            CP_COMMIT();
        }

        const char* As = smem + OFF_A + st * A_STGB;
        const char* Bs = smem + OFF_B + st * B_STGB;

#pragma unroll
        for (int kk = 0; kk < 4; kk++) {
            const int koff = kk * 32;          // bytes (16 halves)
            uint32_t a[4][4];
#pragma unroll
            for (int mt = 0; mt < 4; mt++) {
                const int r = wm * 64 + mt * 16 + gid;
                const char* p0 = As + r * ROWB + koff + tig * 4;
                const char* p1 = As + (r + 8) * ROWB + koff + tig * 4;
                a[mt][0] = *(const uint32_t*)(p0);
                a[mt][1] = *(const uint32_t*)(p1);
                a[mt][2] = *(const uint32_t*)(p0 + 16);
                a[mt][3] = *(const uint32_t*)(p1 + 16);
            }
            uint32_t b[8][2];
#pragma unroll
            for (int nt = 0; nt < 8; nt++) {
                const int nr = wn * 64 + nt * 8 + gid;
                const char* p = Bs + nr * ROWB + koff + tig * 4;
                b[nt][0] = *(const uint32_t*)(p);
                b[nt][1] = *(const uint32_t*)(p + 16);
            }
#pragma unroll
            for (int mt = 0; mt < 4; mt++)
#pragma unroll
                for (int nt = 0; nt < 8; nt++)
                    mma_f16(d[mt][nt], a[mt][0], a[mt][1], a[mt][2], a[mt][3],
                            b[nt][0], b[nt][1]);
        }
    }
    CP_WAIT0();

    // ---- epilogue: fused bias ----
    const float* bs = smf + wn * 64;
#pragma unroll
    for (int mt = 0; mt < 4; mt++) {
        const int r = m0 + wm * 64 + mt * 16 + gid;
        float* o0p = out + (size_t)r * DOUT + n0 + wn * 64;
        float* o1p = o0p + (size_t)8 * DOUT;
#pragma unroll
        for (int nt = 0; nt < 8; nt++) {
            const int col = nt * 8 + tig * 2;
            float2 v0, v1;
            v0.x = d[mt][nt][0] + bs[col];
            v0.y = d[mt][nt][1] + bs[col + 1];
            v1.x = d[mt][nt][2] + bs[col];
            v1.y = d[mt][nt][3] + bs[col + 1];
            *(float2*)(o0p + col) = v0;
            *(float2*)(o1p + col) = v1;
        }
    }
#undef PREFETCH
}

// ---------------------------------------------------------------------------
// launch
// ---------------------------------------------------------------------------
extern "C" void kernel_launch(void* const* d_in, const int* in_sizes, int n_in,
                              void* d_out, int out_size) {
    const float* x      = (const float*)d_in[0];
    const float* weight = (const float*)d_in[1];
    const float* bias   = (const float*)d_in[2];
    const float* lora_A = (const float*)d_in[3];
    const float* lora_B = (const float*)d_in[4];
    const void*  starts = d_in[5];
    float* out = (float*)d_out;
    const int n_starts = in_sizes[5];

    sel_kernel<<<1, 32>>>(starts, n_starts);
    wh_kernel<<<(DOUT * (size_t)DIN / 8) / 256, 256>>>(weight);
    bwhx_kernel<<<((NLORA + 1) * DOUT * BKH) / 256, 256>>>(lora_B);
    xa_kernel<<<MROWS, 128>>>(x, lora_A);

    cudaFuncSetAttribute(gemm_kernel,
                         cudaFuncAttributeMaxDynamicSharedMemorySize, SMEM_BYTES);
    dim3 grid(DOUT / BN, MROWS / BM);  // (16, 128)
    gemm_kernel<<<grid, GTHREADS, SMEM_BYTES>>>(bias, out);
}

// round 8
// speedup vs baseline: 1.9657x; 1.0647x over previous
#include <cuda_runtime.h>
#include <cuda_fp16.h>
#include <cstdint>

// ============================================================================
// MultiLoraLinear — fp16 HMMA path, v5
//   out = x @ W^T + bias + LoRA(per-segment, rank 16)
//
// CRITICAL RULE (root cause of rounds 6/7): NEVER pass a __device__ global as
// a kernel argument from host code — the host-side shadow address is taken,
// and on GB300 (ATS) the kernel silently writes host memory. All kernels
// reference the scratch globals from device code only.
//
//   1) sel_kernel : batch -> weight id (dtype-robust starts read: i32 or i64)
//   2) wh_kernel  : g_wh = half(W)        (device-global ref inside kernel)
//   3) xh_kernel  : g_xh = half(x)
//   4) lah_kernel : [0 | lora_A] fp16 table (slab 0 = zeros)
//   5) bwhx_kernel: [0 | lora_B] fp16 K-ext table (slab 0 = zeros)
//   6) xag_kernel : HMMA mini GEMM  g_xah = [x @ A_sel^T * scale | 0]
//   7) gemm_kernel: 128x256 CTA tiles, K = 65 chunks of 64 halves (last =
//      LoRA ext), 3-stage cp.async, 1 barrier/chunk, ldmatrix.x4 fragment
//      loads, fused bias epilogue.
// ============================================================================

#define DIN      4096
#define DOUT     4096
#define NBATCH   8
#define MROWS    16384
#define RANK     16
#define NLORA    3
#define SCALE_F  1.0f                // alpha / rank

#define BM       128
#define BN       256
#define BKH      64                  // K halves per chunk (= 128 B per row)
#define NCH      (DIN / BKH)         // 64 main chunks
#define NCHT     (NCH + 1)           // +1 LoRA extension chunk
#define GTHREADS 256

// main GEMM SMEM (bytes): bias 256 floats | 3x A stage | 3x B stage
#define ROWB     144                 // padded row stride bytes (72 halves)
#define OFF_A    1024
#define A_STGB   (BM * ROWB)         // 18432
#define OFF_B    (OFF_A + 3 * A_STGB)
#define B_STGB   (BN * ROWB)         // 36864
#define SMEM_BYTES (OFF_B + 3 * B_STGB)   // 166912

// ---------------------------------------------------------------------------
// device scratch (no cudaMalloc allowed; referenced ONLY from device code)
// ---------------------------------------------------------------------------
__device__ __half g_wh[(size_t)DOUT * DIN];                  // 32 MB
__device__ __half g_xh[(size_t)MROWS * DIN];                 // 128 MB
__device__ __half g_xah[(size_t)MROWS * BKH];                // 2 MB [xa|0]
__device__ __half g_bwhx[(size_t)(NLORA + 1) * DOUT * BKH];  // 2 MB
__device__ __half g_lahx[(size_t)(NLORA + 1) * RANK * DIN];  // 512 KB
__device__ int    g_sel[NBATCH];

// ---------------------------------------------------------------------------
// helpers
// ---------------------------------------------------------------------------
__device__ __forceinline__ uint32_t smem_u32(const void* p) {
    uint32_t a;
    asm("{ .reg .u64 t; cvta.to.shared.u64 t, %1; cvt.u32.u64 %0, t; }"
        : "=r"(a) : "l"(p));
    return a;
}

__device__ __forceinline__ void cp_async16(uint32_t dst_smem, const void* src) {
    asm volatile("cp.async.cg.shared.global [%0], [%1], 16;"
                 :: "r"(dst_smem), "l"(src) : "memory");
}
#define CP_COMMIT() asm volatile("cp.async.commit_group;" ::: "memory")
#define CP_WAIT1()  asm volatile("cp.async.wait_group 1;" ::: "memory")
#define CP_WAIT0()  asm volatile("cp.async.wait_group 0;" ::: "memory")

__device__ __forceinline__ void mma_f16(float* d, uint32_t a0, uint32_t a1,
                                        uint32_t a2, uint32_t a3,
                                        uint32_t b0, uint32_t b1) {
    asm volatile(
        "mma.sync.aligned.m16n8k16.row.col.f32.f16.f16.f32 "
        "{%0,%1,%2,%3}, {%4,%5,%6,%7}, {%8,%9}, {%0,%1,%2,%3};"
        : "+f"(d[0]), "+f"(d[1]), "+f"(d[2]), "+f"(d[3])
        : "r"(a0), "r"(a1), "r"(a2), "r"(a3), "r"(b0), "r"(b1));
}

__device__ __forceinline__ void ldsm4(uint32_t& r0, uint32_t& r1,
                                      uint32_t& r2, uint32_t& r3,
                                      uint32_t addr) {
    asm volatile("ldmatrix.sync.aligned.m8n8.x4.shared.b16 {%0,%1,%2,%3}, [%4];"
                 : "=r"(r0), "=r"(r1), "=r"(r2), "=r"(r3) : "r"(addr));
}

// ---------------------------------------------------------------------------
// 1) batch -> weight id.  searchsorted(starts, b, 'right') - 1 semantics.
//    DTYPE-ROBUST: JAX with x64 disabled emits int32 even for "int64".
// ---------------------------------------------------------------------------
__global__ void sel_kernel(const void* __restrict__ starts_raw, int n_starts) {
    const long long* s64 = (const long long*)starts_raw;
    const int*       s32 = (const int*)starts_raw;

    bool ok64 = true;
    long long prev = -1;
    for (int j = 0; j < n_starts; j++) {
        long long v = s64[j];
        if (v < 0 || v >= 64 || v < prev) { ok64 = false; break; }
        prev = v;
    }

    int b = threadIdx.x;
    if (b < NBATCH) {
        int cnt = 0;
        for (int j = 0; j < n_starts; j++) {
            long long v = ok64 ? s64[j] : (long long)s32[j];
            cnt += (v <= (long long)b);
        }
        int seg = cnt - 1;
        int id = 0;
        if (seg > 0) { id = seg; if (id > NLORA) id = NLORA; }
        g_sel[b] = id;
    }
}

// ---------------------------------------------------------------------------
// 2/3) fp32 -> fp16 converts (globals referenced in device code)
// ---------------------------------------------------------------------------
__device__ __forceinline__ void cvt8(const float4* s4, __half* dst, size_t idx) {
    float4 a = s4[2 * idx], b = s4[2 * idx + 1];
    __half2 h[4];
    h[0] = __floats2half2_rn(a.x, a.y);
    h[1] = __floats2half2_rn(a.z, a.w);
    h[2] = __floats2half2_rn(b.x, b.y);
    h[3] = __floats2half2_rn(b.z, b.w);
    *(uint4*)(dst + idx * 8) = *(const uint4*)h;
}

__global__ void __launch_bounds__(256) wh_kernel(const float* __restrict__ W) {
    size_t idx = (size_t)blockIdx.x * 256 + threadIdx.x;
    cvt8((const float4*)W, g_wh, idx);
}

__global__ void __launch_bounds__(256) xh_kernel(const float* __restrict__ x) {
    size_t idx = (size_t)blockIdx.x * 256 + threadIdx.x;
    cvt8((const float4*)x, g_xh, idx);
}

// ---------------------------------------------------------------------------
// 4) lora_A fp16 table with zero slab 0: g_lahx[a][r][k]
// ---------------------------------------------------------------------------
__global__ void __launch_bounds__(256) lah_kernel(const float* __restrict__ lA) {
    int idx = blockIdx.x * 256 + threadIdx.x;   // < 4*16*4096 = 262144
    int a = idx >> 16;                           // / (RANK*DIN)
    float v = 0.0f;
    if (a > 0) v = lA[(size_t)idx - (size_t)RANK * DIN];
    g_lahx[idx] = __float2half_rn(v);
}

// ---------------------------------------------------------------------------
// 5) B-extension: g_bwhx[a][n][c] = (a>0 && c<16) ? half(lora_B[a-1][n][c]) : 0
// ---------------------------------------------------------------------------
__global__ void __launch_bounds__(256) bwhx_kernel(const float* __restrict__ lB) {
    int idx = blockIdx.x * 256 + threadIdx.x;   // < 4*4096*64 = 1048576
    int c = idx & 63;
    int n = (idx >> 6) & (DOUT - 1);
    int a = idx >> 18;
    float v = 0.0f;
    if (a > 0 && c < RANK)
        v = lB[((size_t)(a - 1) * DOUT + n) * RANK + c];
    g_bwhx[idx] = __float2half_rn(v);
}

// ---------------------------------------------------------------------------
// 6) xag: g_xah[m][0:16] = scale * (g_xh[m] @ A_sel^T);  cols 16..63 = 0
//    128 rows / CTA, 8 warps (16 rows each), HMMA m16n8k16,
//    LDS.32 fragment loads, 2-stage cp.async.
// ---------------------------------------------------------------------------
#define XR 144                       // padded row bytes
#define XS_STG (128 * XR)            // 18432
#define AS_STG (16 * XR)             // 2304

__global__ void __launch_bounds__(256) xag_kernel() {
    __shared__ char sm2[2 * XS_STG + 2 * AS_STG];   // 41472 B static
    const int tid  = threadIdx.x;
    const int lane = tid & 31;
    const int wid  = tid >> 5;
    const int gid  = lane >> 2;      // 0..7
    const int tig  = lane & 3;       // 0..3
    const int m0   = blockIdx.x * 128;
    const int sel  = g_sel[m0 >> 11];

    const int rowA = tid >> 3;       // 0..31 (+32*i)
    const int q    = tid & 7;
    const uint32_t sbase = smem_u32(sm2);
    const __half* srcX = g_xh + (size_t)(m0 + rowA) * DIN + q * 8;
    const __half* srcL = g_lahx + (size_t)sel * RANK * DIN
                       + (size_t)(tid >> 3) * DIN + q * 8;
    const uint32_t dstX = sbase + (uint32_t)(rowA * XR + q * 16);
    const uint32_t dstL = sbase + 2 * XS_STG + (uint32_t)((tid >> 3) * XR + q * 16);

#define XPF(cn, st) do {                                                      \
    const __half* _x = srcX + (size_t)(cn) * BKH;                             \
    _Pragma("unroll")                                                         \
    for (int i = 0; i < 4; i++)                                               \
        cp_async16(dstX + (st) * XS_STG + i * (32 * XR),                      \
                   _x + (size_t)(32 * i) * DIN);                              \
    if (tid < 128)                                                            \
        cp_async16(dstL + (st) * AS_STG, srcL + (size_t)(cn) * BKH);          \
} while (0)

    XPF(0, 0); CP_COMMIT();

    float d[2][4];
#pragma unroll
    for (int nt = 0; nt < 2; nt++)
#pragma unroll
        for (int r = 0; r < 4; r++) d[nt][r] = 0.0f;

    for (int c = 0; c < NCH; c++) {
        const int st = c & 1;
        CP_WAIT0();
        __syncthreads();
        if (c + 1 < NCH) { XPF(c + 1, st ^ 1); CP_COMMIT(); }

        const char* Xs = sm2 + st * XS_STG;
        const char* As = sm2 + 2 * XS_STG + st * AS_STG;
#pragma unroll
        for (int kk = 0; kk < 4; kk++) {
            const int koff = kk * 32;           // bytes (16 halves)
            const int r = wid * 16 + gid;
            const char* p0 = Xs + r * XR + koff + tig * 4;
            const char* p1 = Xs + (r + 8) * XR + koff + tig * 4;
            uint32_t a0 = *(const uint32_t*)(p0);
            uint32_t a1 = *(const uint32_t*)(p1);
            uint32_t a2 = *(const uint32_t*)(p0 + 16);
            uint32_t a3 = *(const uint32_t*)(p1 + 16);
            uint32_t b[2][2];
#pragma unroll
            for (int nt = 0; nt < 2; nt++) {
                const char* p = As + (nt * 8 + gid) * XR + koff + tig * 4;
                b[nt][0] = *(const uint32_t*)(p);
                b[nt][1] = *(const uint32_t*)(p + 16);
            }
            mma_f16(d[0], a0, a1, a2, a3, b[0][0], b[0][1]);
            mma_f16(d[1], a0, a1, a2, a3, b[1][0], b[1][1]);
        }
        __syncthreads();              // stage reuse guard before next overwrite
    }

    // epilogue: cols 0..15 from accumulators (std mma d layout), 16..63 zero
#pragma unroll
    for (int nt = 0; nt < 2; nt++) {
        const int col = nt * 8 + tig * 2;
        const int r0 = m0 + wid * 16 + gid;
        __half2 v0 = __floats2half2_rn(d[nt][0] * SCALE_F, d[nt][1] * SCALE_F);
        __half2 v1 = __floats2half2_rn(d[nt][2] * SCALE_F, d[nt][3] * SCALE_F);
        *(__half2*)(g_xah + (size_t)r0 * BKH + col) = v0;
        *(__half2*)(g_xah + (size_t)(r0 + 8) * BKH + col) = v1;
    }
    const uint4 z = {0u, 0u, 0u, 0u};
#pragma unroll
    for (int i = 0; i < 3; i++) {
        int idx = tid + i * 256;               // < 768 = 128 rows * 6 slots
        int row = idx / 6, slot = idx % 6;
        *(uint4*)(g_xah + (size_t)(m0 + row) * BKH + 16 + slot * 8) = z;
    }
#undef XPF
}

// ---------------------------------------------------------------------------
// 7) GEMM: out[m,n] = sum_{65 chunks of 64 halves} A.B + bias[n]
//    3-stage pipeline, 1 barrier/chunk, ldmatrix.x4 fragment loads.
// ---------------------------------------------------------------------------
__global__ void __launch_bounds__(GTHREADS, 1)
gemm_kernel(const float* __restrict__ bias, float* __restrict__ out) {
    extern __shared__ char smem[];
    float* smf = (float*)smem;
    const int tid  = threadIdx.x;
    const int lane = tid & 31;
    const int wid  = tid >> 5;
    const int gid  = lane >> 2;      // 0..7
    const int tig  = lane & 3;       // 0..3
    const int wm   = wid & 1;        // warp M (2)
    const int wn   = wid >> 1;       // warp N (4)

    const int n0 = blockIdx.x * BN;
    const int m0 = blockIdx.y * BM;
    const int sel = g_sel[m0 >> 11];

    smf[tid] = bias[n0 + tid];

    const uint32_t sbase = smem_u32(smem);
    const int rowA = tid >> 3;
    const int q    = tid & 7;
    const __half* srcA  = g_xh + (size_t)(m0 + rowA) * DIN + q * 8;
    const __half* srcB  = g_wh + (size_t)(n0 + rowA) * DIN + q * 8;
    const __half* srcAe = g_xah  + (size_t)(m0 + rowA) * BKH + q * 8;
    const __half* srcBe = g_bwhx + ((size_t)sel * DOUT + (n0 + rowA)) * BKH + q * 8;
    const uint32_t dstA = sbase + OFF_A + (uint32_t)(rowA * ROWB + q * 16);
    const uint32_t dstB = sbase + OFF_B + (uint32_t)(rowA * ROWB + q * 16);

    // per-lane ldmatrix base offsets
    // A x4: lanes 0-7 -> mat0 rows (m 0-7, k-lo), 8-15 -> mat1 (m 8-15, k-lo),
    //       16-23 -> mat2 (m 0-7, k-hi), 24-31 -> mat3 (m 8-15, k-hi)
    const uint32_t aoffl = (uint32_t)((wm * 64 + (lane & 15)) * ROWB
                                      + ((lane >> 4) & 1) * 16);
    // B x4: lanes 0-7 -> (n 0-7, k-lo), 8-15 -> (n 0-7, k-hi),
    //       16-23 -> (n 8-15, k-lo), 24-31 -> (n 8-15, k-hi)
    const uint32_t boffl = (uint32_t)((wn * 64 + ((lane >> 4) & 1) * 8
                                       + (lane & 7)) * ROWB
                                      + ((lane >> 3) & 1) * 16);

#define PREFETCH(cn, st) do {                                                 \
    if ((cn) < NCH) {                                                         \
        const __half* _a = srcA + (size_t)(cn) * BKH;                         \
        const __half* _b = srcB + (size_t)(cn) * BKH;                         \
        _Pragma("unroll")                                                     \
        for (int i = 0; i < 4; i++)                                           \
            cp_async16(dstA + (st) * A_STGB + i * (32 * ROWB),                \
                       _a + (size_t)(32 * i) * DIN);                          \
        _Pragma("unroll")                                                     \
        for (int i = 0; i < 8; i++)                                           \
            cp_async16(dstB + (st) * B_STGB + i * (32 * ROWB),                \
                       _b + (size_t)(32 * i) * DIN);                          \
    } else {                                                                  \
        _Pragma("unroll")                                                     \
        for (int i = 0; i < 4; i++)                                           \
            cp_async16(dstA + (st) * A_STGB + i * (32 * ROWB),                \
                       srcAe + (size_t)(32 * i) * BKH);                       \
        _Pragma("unroll")                                                     \
        for (int i = 0; i < 8; i++)                                           \
            cp_async16(dstB + (st) * B_STGB + i * (32 * ROWB),                \
                       srcBe + (size_t)(32 * i) * BKH);                       \
    }                                                                         \
} while (0)

    PREFETCH(0, 0); CP_COMMIT();
    PREFETCH(1, 1); CP_COMMIT();

    float d[4][8][4];
#pragma unroll
    for (int mt = 0; mt < 4; mt++)
#pragma unroll
        for (int nt = 0; nt < 8; nt++)
#pragma unroll
            for (int r = 0; r < 4; r++) d[mt][nt][r] = 0.0f;

    for (int c = 0; c < NCHT; c++) {
        const int st = c % 3;
        CP_WAIT1();                   // chunk c's group complete
        __syncthreads();              // all warps done with stage (c-1)%3

        {
            int cn = c + 2; if (cn > NCH) cn = NCH;   // clamped duplicate tail
            PREFETCH(cn, (c + 2) % 3);
            CP_COMMIT();
        }

        const uint32_t As = sbase + OFF_A + st * A_STGB;
        const uint32_t Bs = sbase + OFF_B + st * B_STGB;

#pragma unroll
        for (int kk = 0; kk < 4; kk++) {
            const uint32_t koff = kk * 32;
            uint32_t a[4][4];
#pragma unroll
            for (int mt = 0; mt < 4; mt++)
                ldsm4(a[mt][0], a[mt][1], a[mt][2], a[mt][3],
                      As + aoffl + mt * (16 * ROWB) + koff);
            uint32_t b[8][2];
#pragma unroll
            for (int p = 0; p < 4; p++)
                ldsm4(b[2 * p][0], b[2 * p][1], b[2 * p + 1][0], b[2 * p + 1][1],
                      Bs + boffl + p * (16 * ROWB) + koff);
#pragma unroll
            for (int mt = 0; mt < 4; mt++)
#pragma unroll
                for (int nt = 0; nt < 8; nt++)
                    mma_f16(d[mt][nt], a[mt][0], a[mt][1], a[mt][2], a[mt][3],
                            b[nt][0], b[nt][1]);
        }
    }
    CP_WAIT0();

    // ---- epilogue: fused bias ----
    const float* bs = smf + wn * 64;
#pragma unroll
    for (int mt = 0; mt < 4; mt++) {
        const int r = m0 + wm * 64 + mt * 16 + gid;
        float* o0p = out + (size_t)r * DOUT + n0 + wn * 64;
        float* o1p = o0p + (size_t)8 * DOUT;
#pragma unroll
        for (int nt = 0; nt < 8; nt++) {
            const int col = nt * 8 + tig * 2;
            float2 v0, v1;
            v0.x = d[mt][nt][0] + bs[col];
            v0.y = d[mt][nt][1] + bs[col + 1];
            v1.x = d[mt][nt][2] + bs[col];
            v1.y = d[mt][nt][3] + bs[col + 1];
            *(float2*)(o0p + col) = v0;
            *(float2*)(o1p + col) = v1;
        }
    }
#undef PREFETCH
}

// ---------------------------------------------------------------------------
// launch
// ---------------------------------------------------------------------------
extern "C" void kernel_launch(void* const* d_in, const int* in_sizes, int n_in,
                              void* d_out, int out_size) {
    const float* x      = (const float*)d_in[0];
    const float* weight = (const float*)d_in[1];
    const float* bias   = (const float*)d_in[2];
    const float* lora_A = (const float*)d_in[3];
    const float* lora_B = (const float*)d_in[4];
    const void*  starts = d_in[5];
    float* out = (float*)d_out;
    const int n_starts = in_sizes[5];

    sel_kernel<<<1, 32>>>(starts, n_starts);
    wh_kernel<<<(DOUT * (size_t)DIN / 8) / 256, 256>>>(weight);
    xh_kernel<<<(MROWS * (size_t)DIN / 8) / 256, 256>>>(x);
    lah_kernel<<<((NLORA + 1) * RANK * DIN) / 256, 256>>>(lora_A);
    bwhx_kernel<<<((NLORA + 1) * DOUT * BKH) / 256, 256>>>(lora_B);
    xag_kernel<<<MROWS / 128, 256>>>();

    cudaFuncSetAttribute(gemm_kernel,
                         cudaFuncAttributeMaxDynamicSharedMemorySize, SMEM_BYTES);
    dim3 grid(DOUT / BN, MROWS / BM);  // (16, 128)
    gemm_kernel<<<grid, GTHREADS, SMEM_BYTES>>>(bias, out);
}

// round 9
// speedup vs baseline: 2.2287x; 1.1338x over previous
#include <cuda_runtime.h>
#include <cuda_fp16.h>
#include <cstdint>

// ============================================================================
// MultiLoraLinear — fp16 HMMA path, v6 (occupancy-2 GEMM)
//   out = x @ W^T + bias + LoRA(per-segment, rank 16)
//
// CRITICAL RULE: NEVER pass a __device__ global as a kernel argument from
// host code (host-side shadow address; on GB300/ATS it silently writes host
// memory). All scratch globals are referenced from device code only.
//
//   1) sel_kernel : batch -> weight id (dtype-robust starts read: i32 or i64)
//   2) wh_kernel  : g_wh = half(W)
//   3) xh_kernel  : g_xh = half(x)
//   4) lah_kernel : [0 | lora_A] fp16 table (slab 0 = zeros)
//   5) bwhx_kernel: [0 | lora_B] fp16 K-ext table (slab 0 = zeros)
//   6) xag_kernel : HMMA mini GEMM  g_xah = [x @ A_sel^T * scale | 0]
//   7) gemm_kernel: 128x128 CTA tiles (2 CTAs/SM!), K = 65 chunks of 64
//      halves (last = LoRA ext), 3-stage cp.async, 1 barrier/chunk,
//      ldmatrix.x4 fragment loads, fused bias epilogue.
// ============================================================================

#define DIN      4096
#define DOUT     4096
#define NBATCH   8
#define MROWS    16384
#define RANK     16
#define NLORA    3
#define SCALE_F  1.0f                // alpha / rank

#define BM       128
#define BN       128
#define BKH      64                  // K halves per chunk (= 128 B per row)
#define NCH      (DIN / BKH)         // 64 main chunks
#define NCHT     (NCH + 1)           // +1 LoRA extension chunk
#define GTHREADS 256

// GEMM SMEM (bytes): bias 128 floats | 3x A stage | 3x B stage
#define ROWB     144                 // padded row stride bytes (72 halves)
#define OFF_A    1024
#define A_STGB   (BM * ROWB)         // 18432
#define OFF_B    (OFF_A + 3 * A_STGB)
#define B_STGB   (BN * ROWB)         // 18432
#define SMEM_BYTES (OFF_B + 3 * B_STGB)   // 111616  -> 2 CTAs/SM

// ---------------------------------------------------------------------------
// device scratch (no cudaMalloc allowed; referenced ONLY from device code)
// ---------------------------------------------------------------------------
__device__ __half g_wh[(size_t)DOUT * DIN];                  // 32 MB
__device__ __half g_xh[(size_t)MROWS * DIN];                 // 128 MB
__device__ __half g_xah[(size_t)MROWS * BKH];                // 2 MB [xa|0]
__device__ __half g_bwhx[(size_t)(NLORA + 1) * DOUT * BKH];  // 2 MB
__device__ __half g_lahx[(size_t)(NLORA + 1) * RANK * DIN];  // 512 KB
__device__ int    g_sel[NBATCH];

// ---------------------------------------------------------------------------
// helpers
// ---------------------------------------------------------------------------
__device__ __forceinline__ uint32_t smem_u32(const void* p) {
    uint32_t a;
    asm("{ .reg .u64 t; cvta.to.shared.u64 t, %1; cvt.u32.u64 %0, t; }"
        : "=r"(a) : "l"(p));
    return a;
}

__device__ __forceinline__ void cp_async16(uint32_t dst_smem, const void* src) {
    asm volatile("cp.async.cg.shared.global [%0], [%1], 16;"
                 :: "r"(dst_smem), "l"(src) : "memory");
}
#define CP_COMMIT() asm volatile("cp.async.commit_group;" ::: "memory")
#define CP_WAIT1()  asm volatile("cp.async.wait_group 1;" ::: "memory")
#define CP_WAIT0()  asm volatile("cp.async.wait_group 0;" ::: "memory")

__device__ __forceinline__ void mma_f16(float* d, uint32_t a0, uint32_t a1,
                                        uint32_t a2, uint32_t a3,
                                        uint32_t b0, uint32_t b1) {
    asm volatile(
        "mma.sync.aligned.m16n8k16.row.col.f32.f16.f16.f32 "
        "{%0,%1,%2,%3}, {%4,%5,%6,%7}, {%8,%9}, {%0,%1,%2,%3};"
        : "+f"(d[0]), "+f"(d[1]), "+f"(d[2]), "+f"(d[3])
        : "r"(a0), "r"(a1), "r"(a2), "r"(a3), "r"(b0), "r"(b1));
}

__device__ __forceinline__ void ldsm4(uint32_t& r0, uint32_t& r1,
                                      uint32_t& r2, uint32_t& r3,
                                      uint32_t addr) {
    asm volatile("ldmatrix.sync.aligned.m8n8.x4.shared.b16 {%0,%1,%2,%3}, [%4];"
                 : "=r"(r0), "=r"(r1), "=r"(r2), "=r"(r3) : "r"(addr));
}

// ---------------------------------------------------------------------------
// 1) batch -> weight id.  searchsorted(starts, b, 'right') - 1 semantics.
//    DTYPE-ROBUST: JAX with x64 disabled emits int32 even for "int64".
// ---------------------------------------------------------------------------
__global__ void sel_kernel(const void* __restrict__ starts_raw, int n_starts) {
    const long long* s64 = (const long long*)starts_raw;
    const int*       s32 = (const int*)starts_raw;

    bool ok64 = true;
    long long prev = -1;
    for (int j = 0; j < n_starts; j++) {
        long long v = s64[j];
        if (v < 0 || v >= 64 || v < prev) { ok64 = false; break; }
        prev = v;
    }

    int b = threadIdx.x;
    if (b < NBATCH) {
        int cnt = 0;
        for (int j = 0; j < n_starts; j++) {
            long long v = ok64 ? s64[j] : (long long)s32[j];
            cnt += (v <= (long long)b);
        }
        int seg = cnt - 1;
        int id = 0;
        if (seg > 0) { id = seg; if (id > NLORA) id = NLORA; }
        g_sel[b] = id;
    }
}

// ---------------------------------------------------------------------------
// 2/3) fp32 -> fp16 converts (globals referenced in device code)
// ---------------------------------------------------------------------------
__device__ __forceinline__ void cvt8(const float4* s4, __half* dst, size_t idx) {
    float4 a = s4[2 * idx], b = s4[2 * idx + 1];
    __half2 h[4];
    h[0] = __floats2half2_rn(a.x, a.y);
    h[1] = __floats2half2_rn(a.z, a.w);
    h[2] = __floats2half2_rn(b.x, b.y);
    h[3] = __floats2half2_rn(b.z, b.w);
    *(uint4*)(dst + idx * 8) = *(const uint4*)h;
}

__global__ void __launch_bounds__(256) wh_kernel(const float* __restrict__ W) {
    size_t idx = (size_t)blockIdx.x * 256 + threadIdx.x;
    cvt8((const float4*)W, g_wh, idx);
}

__global__ void __launch_bounds__(256) xh_kernel(const float* __restrict__ x) {
    size_t idx = (size_t)blockIdx.x * 256 + threadIdx.x;
    cvt8((const float4*)x, g_xh, idx);
}

// ---------------------------------------------------------------------------
// 4) lora_A fp16 table with zero slab 0: g_lahx[a][r][k]
// ---------------------------------------------------------------------------
__global__ void __launch_bounds__(256) lah_kernel(const float* __restrict__ lA) {
    int idx = blockIdx.x * 256 + threadIdx.x;   // < 4*16*4096 = 262144
    int a = idx >> 16;                           // / (RANK*DIN)
    float v = 0.0f;
    if (a > 0) v = lA[(size_t)idx - (size_t)RANK * DIN];
    g_lahx[idx] = __float2half_rn(v);
}

// ---------------------------------------------------------------------------
// 5) B-extension: g_bwhx[a][n][c] = (a>0 && c<16) ? half(lora_B[a-1][n][c]) : 0
// ---------------------------------------------------------------------------
__global__ void __launch_bounds__(256) bwhx_kernel(const float* __restrict__ lB) {
    int idx = blockIdx.x * 256 + threadIdx.x;   // < 4*4096*64 = 1048576
    int c = idx & 63;
    int n = (idx >> 6) & (DOUT - 1);
    int a = idx >> 18;
    float v = 0.0f;
    if (a > 0 && c < RANK)
        v = lB[((size_t)(a - 1) * DOUT + n) * RANK + c];
    g_bwhx[idx] = __float2half_rn(v);
}

// ---------------------------------------------------------------------------
// 6) xag: g_xah[m][0:16] = scale * (g_xh[m] @ A_sel^T);  cols 16..63 = 0
//    128 rows / CTA, 8 warps (16 rows each), HMMA m16n8k16,
//    LDS.32 fragment loads, 2-stage cp.async.
// ---------------------------------------------------------------------------
#define XR 144                       // padded row bytes
#define XS_STG (128 * XR)            // 18432
#define AS_STG (16 * XR)             // 2304

__global__ void __launch_bounds__(256) xag_kernel() {
    __shared__ char sm2[2 * XS_STG + 2 * AS_STG];   // 41472 B static
    const int tid  = threadIdx.x;
    const int lane = tid & 31;
    const int wid  = tid >> 5;
    const int gid  = lane >> 2;      // 0..7
    const int tig  = lane & 3;       // 0..3
    const int m0   = blockIdx.x * 128;
    const int sel  = g_sel[m0 >> 11];

    const int rowA = tid >> 3;       // 0..31 (+32*i)
    const int q    = tid & 7;
    const uint32_t sbase = smem_u32(sm2);
    const __half* srcX = g_xh + (size_t)(m0 + rowA) * DIN + q * 8;
    const __half* srcL = g_lahx + (size_t)sel * RANK * DIN
                       + (size_t)(tid >> 3) * DIN + q * 8;
    const uint32_t dstX = sbase + (uint32_t)(rowA * XR + q * 16);
    const uint32_t dstL = sbase + 2 * XS_STG + (uint32_t)((tid >> 3) * XR + q * 16);

#define XPF(cn, st) do {                                                      \
    const __half* _x = srcX + (size_t)(cn) * BKH;                             \
    _Pragma("unroll")                                                         \
    for (int i = 0; i < 4; i++)                                               \
        cp_async16(dstX + (st) * XS_STG + i * (32 * XR),                      \
                   _x + (size_t)(32 * i) * DIN);                              \
    if (tid < 128)                                                            \
        cp_async16(dstL + (st) * AS_STG, srcL + (size_t)(cn) * BKH);          \
} while (0)

    XPF(0, 0); CP_COMMIT();

    float d[2][4];
#pragma unroll
    for (int nt = 0; nt < 2; nt++)
#pragma unroll
        for (int r = 0; r < 4; r++) d[nt][r] = 0.0f;

    for (int c = 0; c < NCH; c++) {
        const int st = c & 1;
        CP_WAIT0();
        __syncthreads();
        if (c + 1 < NCH) { XPF(c + 1, st ^ 1); CP_COMMIT(); }

        const char* Xs = sm2 + st * XS_STG;
        const char* As = sm2 + 2 * XS_STG + st * AS_STG;
#pragma unroll
        for (int kk = 0; kk < 4; kk++) {
            const int koff = kk * 32;           // bytes (16 halves)
            const int r = wid * 16 + gid;
            const char* p0 = Xs + r * XR + koff + tig * 4;
            const char* p1 = Xs + (r + 8) * XR + koff + tig * 4;
            uint32_t a0 = *(const uint32_t*)(p0);
            uint32_t a1 = *(const uint32_t*)(p1);
            uint32_t a2 = *(const uint32_t*)(p0 + 16);
            uint32_t a3 = *(const uint32_t*)(p1 + 16);
            uint32_t b[2][2];
#pragma unroll
            for (int nt = 0; nt < 2; nt++) {
                const char* p = As + (nt * 8 + gid) * XR + koff + tig * 4;
                b[nt][0] = *(const uint32_t*)(p);
                b[nt][1] = *(const uint32_t*)(p + 16);
            }
            mma_f16(d[0], a0, a1, a2, a3, b[0][0], b[0][1]);
            mma_f16(d[1], a0, a1, a2, a3, b[1][0], b[1][1]);
        }
        __syncthreads();              // stage reuse guard before next overwrite
    }

    // epilogue: cols 0..15 from accumulators (std mma d layout), 16..63 zero
#pragma unroll
    for (int nt = 0; nt < 2; nt++) {
        const int col = nt * 8 + tig * 2;
        const int r0 = m0 + wid * 16 + gid;
        __half2 v0 = __floats2half2_rn(d[nt][0] * SCALE_F, d[nt][1] * SCALE_F);
        __half2 v1 = __floats2half2_rn(d[nt][2] * SCALE_F, d[nt][3] * SCALE_F);
        *(__half2*)(g_xah + (size_t)r0 * BKH + col) = v0;
        *(__half2*)(g_xah + (size_t)(r0 + 8) * BKH + col) = v1;
    }
    const uint4 z = {0u, 0u, 0u, 0u};
#pragma unroll
    for (int i = 0; i < 3; i++) {
        int idx = tid + i * 256;               // < 768 = 128 rows * 6 slots
        int row = idx / 6, slot = idx % 6;
        *(uint4*)(g_xah + (size_t)(m0 + row) * BKH + 16 + slot * 8) = z;
    }
#undef XPF
}

// ---------------------------------------------------------------------------
// 7) GEMM: out[m,n] = sum_{65 chunks of 64 halves} A.B + bias[n]
//    128x128 tiles, 2 CTAs/SM, 3-stage pipeline, ldmatrix.x4 loads.
//    8 warps on 2(M) x 4(N): warp tile 64x32 -> 64 accum regs/thread.
// ---------------------------------------------------------------------------
__global__ void __launch_bounds__(GTHREADS, 2)
gemm_kernel(const float* __restrict__ bias, float* __restrict__ out) {
    extern __shared__ char smem[];
    float* smf = (float*)smem;
    const int tid  = threadIdx.x;
    const int lane = tid & 31;
    const int wid  = tid >> 5;
    const int gid  = lane >> 2;      // 0..7
    const int tig  = lane & 3;       // 0..3
    const int wm   = wid & 1;        // warp M (2)
    const int wn   = wid >> 1;       // warp N (4)

    const int n0 = blockIdx.x * BN;
    const int m0 = blockIdx.y * BM;
    const int sel = g_sel[m0 >> 11];

    if (tid < BN) smf[tid] = bias[n0 + tid];

    const uint32_t sbase = smem_u32(smem);
    const int rowA = tid >> 3;       // 0..31 (+32*i)
    const int q    = tid & 7;        // 16B slot within 128B row
    const __half* srcA  = g_xh + (size_t)(m0 + rowA) * DIN + q * 8;
    const __half* srcB  = g_wh + (size_t)(n0 + rowA) * DIN + q * 8;
    const __half* srcAe = g_xah  + (size_t)(m0 + rowA) * BKH + q * 8;
    const __half* srcBe = g_bwhx + ((size_t)sel * DOUT + (n0 + rowA)) * BKH + q * 8;
    const uint32_t dstA = sbase + OFF_A + (uint32_t)(rowA * ROWB + q * 16);
    const uint32_t dstB = sbase + OFF_B + (uint32_t)(rowA * ROWB + q * 16);

    // per-lane ldmatrix base offsets (same proven maps as round 8)
    const uint32_t aoffl = (uint32_t)((wm * 64 + (lane & 15)) * ROWB
                                      + ((lane >> 4) & 1) * 16);
    const uint32_t boffl = (uint32_t)((wn * 32 + ((lane >> 4) & 1) * 8
                                       + (lane & 7)) * ROWB
                                      + ((lane >> 3) & 1) * 16);

#define PREFETCH(cn, st) do {                                                 \
    if ((cn) < NCH) {                                                         \
        const __half* _a = srcA + (size_t)(cn) * BKH;                         \
        const __half* _b = srcB + (size_t)(cn) * BKH;                         \
        _Pragma("unroll")                                                     \
        for (int i = 0; i < 4; i++)                                           \
            cp_async16(dstA + (st) * A_STGB + i * (32 * ROWB),                \
                       _a + (size_t)(32 * i) * DIN);                          \
        _Pragma("unroll")                                                     \
        for (int i = 0; i < 4; i++)                                           \
            cp_async16(dstB + (st) * B_STGB + i * (32 * ROWB),                \
                       _b + (size_t)(32 * i) * DIN);                          \
    } else {                                                                  \
        _Pragma("unroll")                                                     \
        for (int i = 0; i < 4; i++)                                           \
            cp_async16(dstA + (st) * A_STGB + i * (32 * ROWB),                \
                       srcAe + (size_t)(32 * i) * BKH);                       \
        _Pragma("unroll")                                                     \
        for (int i = 0; i < 4; i++)                                           \
            cp_async16(dstB + (st) * B_STGB + i * (32 * ROWB),                \
                       srcBe + (size_t)(32 * i) * BKH);                       \
    }                                                                         \
} while (0)

    PREFETCH(0, 0); CP_COMMIT();
    PREFETCH(1, 1); CP_COMMIT();

    float d[4][4][4];
#pragma unroll
    for (int mt = 0; mt < 4; mt++)
#pragma unroll
        for (int nt = 0; nt < 4; nt++)
#pragma unroll
            for (int r = 0; r < 4; r++) d[mt][nt][r] = 0.0f;

    for (int c = 0; c < NCHT; c++) {
        const int st = c % 3;
        CP_WAIT1();                   // chunk c's group complete
        __syncthreads();              // all warps done with stage (c-1)%3

        {
            int cn = c + 2; if (cn > NCH) cn = NCH;   // clamped duplicate tail
            PREFETCH(cn, (c + 2) % 3);
            CP_COMMIT();
        }

        const uint32_t As = sbase + OFF_A + st * A_STGB;
        const uint32_t Bs = sbase + OFF_B + st * B_STGB;

#pragma unroll
        for (int kk = 0; kk < 4; kk++) {
            const uint32_t koff = kk * 32;
            uint32_t a[4][4];
#pragma unroll
            for (int mt = 0; mt < 4; mt++)
                ldsm4(a[mt][0], a[mt][1], a[mt][2], a[mt][3],
                      As + aoffl + mt * (16 * ROWB) + koff);
            uint32_t b[4][2];
#pragma unroll
            for (int p = 0; p < 2; p++)
                ldsm4(b[2 * p][0], b[2 * p][1], b[2 * p + 1][0], b[2 * p + 1][1],
                      Bs + boffl + p * (16 * ROWB) + koff);
#pragma unroll
            for (int mt = 0; mt < 4; mt++)
#pragma unroll
                for (int nt = 0; nt < 4; nt++)
                    mma_f16(d[mt][nt], a[mt][0], a[mt][1], a[mt][2], a[mt][3],
                            b[nt][0], b[nt][1]);
        }
    }
    CP_WAIT0();

    // ---- epilogue: fused bias ----
    const float* bs = smf + wn * 32;
#pragma unroll
    for (int mt = 0; mt < 4; mt++) {
        const int r = m0 + wm * 64 + mt * 16 + gid;
        float* o0p = out + (size_t)r * DOUT + n0 + wn * 32;
        float* o1p = o0p + (size_t)8 * DOUT;
#pragma unroll
        for (int nt = 0; nt < 4; nt++) {
            const int col = nt * 8 + tig * 2;
            float2 v0, v1;
            v0.x = d[mt][nt][0] + bs[col];
            v0.y = d[mt][nt][1] + bs[col + 1];
            v1.x = d[mt][nt][2] + bs[col];
            v1.y = d[mt][nt][3] + bs[col + 1];
            *(float2*)(o0p + col) = v0;
            *(float2*)(o1p + col) = v1;
        }
    }
#undef PREFETCH
}

// ---------------------------------------------------------------------------
// launch
// ---------------------------------------------------------------------------
extern "C" void kernel_launch(void* const* d_in, const int* in_sizes, int n_in,
                              void* d_out, int out_size) {
    const float* x      = (const float*)d_in[0];
    const float* weight = (const float*)d_in[1];
    const float* bias   = (const float*)d_in[2];
    const float* lora_A = (const float*)d_in[3];
    const float* lora_B = (const float*)d_in[4];
    const void*  starts = d_in[5];
    float* out = (float*)d_out;
    const int n_starts = in_sizes[5];

    sel_kernel<<<1, 32>>>(starts, n_starts);
    wh_kernel<<<(DOUT * (size_t)DIN / 8) / 256, 256>>>(weight);
    xh_kernel<<<(MROWS * (size_t)DIN / 8) / 256, 256>>>(x);
    lah_kernel<<<((NLORA + 1) * RANK * DIN) / 256, 256>>>(lora_A);
    bwhx_kernel<<<((NLORA + 1) * DOUT * BKH) / 256, 256>>>(lora_B);
    xag_kernel<<<MROWS / 128, 256>>>();

    cudaFuncSetAttribute(gemm_kernel,
                         cudaFuncAttributeMaxDynamicSharedMemorySize, SMEM_BYTES);
    dim3 grid(DOUT / BN, MROWS / BM);  // (32, 128)
    gemm_kernel<<<grid, GTHREADS, SMEM_BYTES>>>(bias, out);
}